// round 14
// baseline (speedup 1.0000x reference)
#include <cuda_runtime.h>

#define DEGREE   6
#define WIDTH    7          // DEGREE - START_DEGREE + 1
#define FEAT     1024       // in_features
#define OUTF     1024       // out_features
#define THREADS  256
#define RPB      4          // rows per block (2 warps per row)
#define GRID     1024       // 4096/4; 7 blocks/SM -> single wave

__device__ __forceinline__ float ex2f(float x) {
    float r; asm("ex2.approx.f32 %0, %1;" : "=f"(r) : "f"(x)); return r;
}
__device__ __forceinline__ float clipf(float v) {
    return fminf(fmaxf(v, -100.0f), 100.0f);
}

// 2-warps-per-row, 7-blocks/SM kernel: 8192 warps ALL doing eval at once
// (vs 4096 with warp-per-row) -> eval-phase latency actually hidden.
// regs forced <= 36: coeffs are NOT register-resident; phase 2 re-reads them
// per row from global (28KB table stays L1-hot; latency ~39cyc, 56 warps/SM).
__global__ __launch_bounds__(THREADS, 7)
void hermite_fused_kernel(const float* __restrict__ x,
                          const float* __restrict__ coeffs,
                          const float* __restrict__ sigma,
                          float* __restrict__ out)
{
    __shared__ float s_part[8][WIDTH];     // per-warp half-row partials
    __shared__ float s_basis[RPB][8];      // merged basis, padded to 8

    const int tid  = threadIdx.x;
    const int lane = tid & 31;
    const int warp = tid >> 5;

    const float s     = fminf(fmaxf(sigma[0], 0.1f), 5.0f);
    const float inv_s = 1.0f / s;
    const float kexp  = -1.4426950408889634f * inv_s * inv_s;  // -log2e/s^2

    // ---- Phase 1: half a row per warp (16 features/lane) ----
    const int row  = blockIdx.x * RPB + (warp >> 1);
    const int half = warp & 1;
    const float4* xr = reinterpret_cast<const float4*>(x + (size_t)row * FEAT)
                       + half * (FEAT / 8);   // 128 float4 per half

    float4 xv[4];
#pragma unroll
    for (int i = 0; i < 4; ++i) xv[i] = xr[lane + 32 * i];

    float a[WIDTH];
#pragma unroll
    for (int w = 0; w < WIDTH; ++w) a[w] = 0.0f;

#pragma unroll
    for (int i = 0; i < 4; ++i) {
        const float xe[4] = { xv[i].x, xv[i].y, xv[i].z, xv[i].w };
#pragma unroll
        for (int e = 0; e < 4; ++e) {
            const float xq  = xe[e];
            const float txs = xq * (2.0f * inv_s);   // 2*xs = H1
            // g = exp(-xs^2); min(xs^2,50) never binds (delta ~e-50 << tol)
            const float g   = ex2f(xq * xq * kexp);

            a[0] += g;                               // g * H0
            a[1] += g * txs;                         // g * H1

            float hm2 = txs;
            float h   = txs * txs - 2.0f;            // H2: clip can't bind
            a[2] += g * h;                           //  where g > 8e-12
            float hm1 = h;
#pragma unroll
            for (int n = 3; n <= DEGREE; ++n) {
                float t = (-2.0f * (float)(n - 1)) * hm2;  // FMUL-imm
                h = fmaf(txs, hm1, t);
                h = clipf(h);                        // clip BEFORE recursion use
                a[n] += g * h;
                hm2 = hm1;
                hm1 = h;
            }
        }
    }

    // ---- warp-local reduction of the 7 accumulators ----
#pragma unroll
    for (int w = 0; w < WIDTH; ++w) {
#pragma unroll
        for (int off = 16; off > 0; off >>= 1)
            a[w] += __shfl_xor_sync(0xffffffffu, a[w], off);
    }
    if (lane == 0) {
#pragma unroll
        for (int w = 0; w < WIDTH; ++w)
            s_part[warp][w] = a[w];
    }

    __syncthreads();   // barrier 1: partials visible

    // ---- merge the two half-row partials (threads 0..27) ----
    if (tid < RPB * WIDTH) {
        const int r = tid / WIDTH;
        const int w = tid - r * WIDTH;
        s_basis[r][w] = s_part[2 * r][w] + s_part[2 * r + 1][w];
    }

    __syncthreads();   // barrier 2: basis ready

    // ---- Phase 2: 4 rows x 4 output columns per thread ----
    // Coeffs re-read per row from global: 28 contiguous floats = 7x LDG.128,
    // L1-resident after the first row of the first block on each SM.
    const float4* c4 = reinterpret_cast<const float4*>(
        coeffs + (size_t)(tid * 4) * WIDTH);
    float* outb = out + (size_t)(blockIdx.x * RPB) * OUTF;

#pragma unroll
    for (int r = 0; r < RPB; ++r) {
        const float4 b0 = *reinterpret_cast<const float4*>(&s_basis[r][0]);
        const float4 b1 = *reinterpret_cast<const float4*>(&s_basis[r][4]);
        const float bs[WIDTH] = { b0.x, b0.y, b0.z, b0.w, b1.x, b1.y, b1.z };

        float4 c[7];
#pragma unroll
        for (int i = 0; i < 7; ++i) c[i] = c4[i];    // L1 hits
        const float* cf = reinterpret_cast<const float*>(c);

        float4 o;
        float* op = reinterpret_cast<float*>(&o);
#pragma unroll
        for (int i = 0; i < 4; ++i) {
            float v = 0.0f;
#pragma unroll
            for (int w = 0; w < WIDTH; ++w)
                v += bs[w] * cf[i * WIDTH + w];
            op[i] = v;
        }
        reinterpret_cast<float4*>(outb + (size_t)r * OUTF)[tid] = o;
    }
}

extern "C" void kernel_launch(void* const* d_in, const int* in_sizes, int n_in,
                              void* d_out, int out_size)
{
    const float* x      = (const float*)d_in[0];   // (4096, 1024)
    const float* coeffs = (const float*)d_in[1];   // (1024, 7)
    const float* sigma  = (const float*)d_in[2];   // (1,)
    float* out          = (float*)d_out;           // (4096, 1024)

    hermite_fused_kernel<<<GRID, THREADS>>>(x, coeffs, sigma, out);
}

// round 15
// speedup vs baseline: 1.0019x; 1.0019x over previous
#include <cuda_runtime.h>

#define DEGREE   6
#define WIDTH    7          // DEGREE - START_DEGREE + 1
#define FEAT     1024       // in_features
#define OUTF     1024       // out_features
#define BATCH    4096

// scratch: per row, two 8-float partial records (halves of the feature dim)
__device__ float g_scratch[BATCH * 16];

__device__ __forceinline__ float ex2f(float x) {
    float r; asm("ex2.approx.f32 %0, %1;" : "=f"(r) : "f"(x)); return r;
}
__device__ __forceinline__ float clipf(float v) {
    return fminf(fmaxf(v, -100.0f), 100.0f);
}

// =================== Kernel A: eval + reduce only =========================
// 8 warps/block, each warp owns one half-row (512 feats, 16/lane).
// No smem, no barrier, no coeffs -> minimal registers, max concurrency:
// 1024 blocks @ 7/SM = single wave, 8192 warps all in eval.
__global__ __launch_bounds__(256, 7)
void hermite_eval_kernel(const float* __restrict__ x,
                         const float* __restrict__ sigma)
{
    const int tid  = threadIdx.x;
    const int lane = tid & 31;
    const int warp = tid >> 5;

    const float s     = fminf(fmaxf(sigma[0], 0.1f), 5.0f);
    const float inv_s = 1.0f / s;
    const float kexp  = -1.4426950408889634f * inv_s * inv_s;  // -log2e/s^2

    const int row  = blockIdx.x * 4 + (warp >> 1);
    const int half = warp & 1;
    const float4* xr = reinterpret_cast<const float4*>(x + (size_t)row * FEAT)
                       + half * (FEAT / 8);   // 128 float4 per half

    float4 xv[4];
#pragma unroll
    for (int i = 0; i < 4; ++i) xv[i] = xr[lane + 32 * i];

    float a[WIDTH];
#pragma unroll
    for (int w = 0; w < WIDTH; ++w) a[w] = 0.0f;

#pragma unroll
    for (int i = 0; i < 4; ++i) {
        const float xe[4] = { xv[i].x, xv[i].y, xv[i].z, xv[i].w };
#pragma unroll
        for (int e = 0; e < 4; ++e) {
            const float xq  = xe[e];
            const float txs = xq * (2.0f * inv_s);   // 2*xs = H1
            // g = exp(-xs^2); min(xs^2,50) never binds (delta ~e-50 << tol)
            const float g   = ex2f(xq * xq * kexp);

            a[0] += g;                               // g * H0
            a[1] += g * txs;                         // g * H1

            float hm2 = txs;
            float h   = txs * txs - 2.0f;            // H2: clip can't bind
            a[2] += g * h;                           //  where g > 8e-12
            float hm1 = h;
#pragma unroll
            for (int n = 3; n <= DEGREE; ++n) {
                float t = (-2.0f * (float)(n - 1)) * hm2;  // FMUL-imm
                h = fmaf(txs, hm1, t);
                h = clipf(h);                        // clip BEFORE recursion use
                a[n] += g * h;
                hm2 = hm1;
                hm1 = h;
            }
        }
    }

    // warp-local butterfly reduction -> full half-row sums in every lane
#pragma unroll
    for (int w = 0; w < WIDTH; ++w) {
#pragma unroll
        for (int off = 16; off > 0; off >>= 1)
            a[w] += __shfl_xor_sync(0xffffffffu, a[w], off);
    }
    if (lane == 0) {
        float4* rec = reinterpret_cast<float4*>(g_scratch + row * 16 + half * 8);
        rec[0] = make_float4(a[0], a[1], a[2], a[3]);
        rec[1] = make_float4(a[4], a[5], a[6], 0.0f);
    }
}

// =================== Kernel B: tiny contraction + 16MB write ==============
// 8 rows per block; coeffs register-resident (28 floats / thread, loaded
// once); per row: merge the two partial records, 28 FFMA, one STG.128.
__global__ __launch_bounds__(256)
void hermite_out_kernel(const float* __restrict__ coeffs,
                        float* __restrict__ out)
{
    const int tid = threadIdx.x;

    // thread owns output columns [4*tid, 4*tid+3]: 28 contiguous coeffs
    float4 c[7];
    {
        const float4* c4 = reinterpret_cast<const float4*>(
            coeffs + (size_t)(tid * 4) * WIDTH);
#pragma unroll
        for (int i = 0; i < 7; ++i) c[i] = c4[i];
    }
    const float* cf = reinterpret_cast<const float*>(c);

    const int row0 = blockIdx.x * 8;
    float* outb = out + (size_t)row0 * OUTF;

#pragma unroll
    for (int r = 0; r < 8; ++r) {
        const float4* rec = reinterpret_cast<const float4*>(
            g_scratch + (row0 + r) * 16);
        const float4 p0 = rec[0];   // L2-resident (256KB scratch)
        const float4 p1 = rec[1];
        const float4 q0 = rec[2];
        const float4 q1 = rec[3];

        const float bs[WIDTH] = {
            p0.x + q0.x, p0.y + q0.y, p0.z + q0.z, p0.w + q0.w,
            p1.x + q1.x, p1.y + q1.y, p1.z + q1.z
        };

        float4 o;
        float* op = reinterpret_cast<float*>(&o);
#pragma unroll
        for (int i = 0; i < 4; ++i) {
            float v = 0.0f;
#pragma unroll
            for (int w = 0; w < WIDTH; ++w)
                v += bs[w] * cf[i * WIDTH + w];
            op[i] = v;
        }
        reinterpret_cast<float4*>(outb + (size_t)r * OUTF)[tid] = o;
    }
}

extern "C" void kernel_launch(void* const* d_in, const int* in_sizes, int n_in,
                              void* d_out, int out_size)
{
    const float* x      = (const float*)d_in[0];   // (4096, 1024)
    const float* coeffs = (const float*)d_in[1];   // (1024, 7)
    const float* sigma  = (const float*)d_in[2];   // (1,)
    float* out          = (float*)d_out;           // (4096, 1024)

    hermite_eval_kernel<<<BATCH / 4, 256>>>(x, sigma);       // 1024 blocks
    hermite_out_kernel<<<BATCH / 8, 256>>>(coeffs, out);     // 512 blocks
}

// round 16
// speedup vs baseline: 1.3400x; 1.3375x over previous
#include <cuda_runtime.h>

#define DEGREE   6
#define WIDTH    7          // DEGREE - START_DEGREE + 1
#define FEAT     1024       // in_features
#define OUTF     1024       // out_features
#define THREADS  256
#define BATCH    4096
#define GRID     592        // 148 SMs x 4 blocks, ONE wave, uniform 4/SM
#define MAXROWS  7          // ceil(4096/592)

typedef unsigned long long u64;
union uf2 { u64 u; float2 f; };

__device__ __forceinline__ float ex2f(float x) {
    float r; asm("ex2.approx.f32 %0, %1;" : "=f"(r) : "f"(x)); return r;
}
__device__ __forceinline__ float clipf(float v) {
    return fminf(fmaxf(v, -100.0f), 100.0f);
}
__device__ __forceinline__ u64 pack2(float lo, float hi) {
    u64 r; asm("mov.b64 %0, {%1, %2};" : "=l"(r) : "f"(lo), "f"(hi)); return r;
}
__device__ __forceinline__ u64 fma2(u64 a, u64 b, u64 c) {
    u64 r; asm("fma.rn.f32x2 %0, %1, %2, %3;" : "=l"(r) : "l"(a), "l"(b), "l"(c)); return r;
}

// Eval of one full row (32 feats/lane). UNIT=true: sigma==1 -> the two
// front multiplies use IMMEDIATE operands (fma-pipe rt 1 vs 2).
template<bool UNIT>
__device__ __forceinline__ void eval_row(const float4* __restrict__ xr,
                                         int lane, float inv_s, float kexp,
                                         float* __restrict__ a)
{
    float4 xv[8];
#pragma unroll
    for (int i = 0; i < 8; ++i) xv[i] = xr[lane + 32 * i];

#pragma unroll
    for (int w = 0; w < WIDTH; ++w) a[w] = 0.0f;

#pragma unroll
    for (int i = 0; i < 8; ++i) {
        const float xe[4] = { xv[i].x, xv[i].y, xv[i].z, xv[i].w };
#pragma unroll
        for (int e = 0; e < 4; ++e) {
            const float xq = xe[e];
            float txs, g;
            if (UNIT) {
                txs = xq * 2.0f;                          // FMUL-imm, rt 1
                g   = ex2f((xq * xq) * -1.4426950408889634f); // rt2 + rt1
            } else {
                txs = xq * (2.0f * inv_s);
                g   = ex2f(xq * xq * kexp);
            }
            // g = exp(-xs^2); min(xs^2,50) never binds (delta ~e-50 << tol)
            a[0] += g;                               // g * H0
            a[1] += g * txs;                         // g * H1

            float hm2 = txs;
            float h   = txs * txs - 2.0f;            // H2: clip can't bind
            a[2] += g * h;                           //  where g > 8e-12
            float hm1 = h;
#pragma unroll
            for (int n = 3; n <= DEGREE; ++n) {
                float t = (-2.0f * (float)(n - 1)) * hm2;  // FMUL-imm, rt 1
                h = fmaf(txs, hm1, t);
                h = clipf(h);                        // clip BEFORE recursion use
                a[n] += g * h;
                hm2 = hm1;
                hm1 = h;
            }
        }
    }
}

// R13 shell (equal-work warp-per-row) + sigma-specialized eval +
// packed-f32x2 phase 2 (halves phase-2 fma-pipe demand).
__global__ __launch_bounds__(THREADS, 4)   // regs <= 64; 4 blocks/SM
void hermite_fused_kernel(const float* __restrict__ x,
                          const float* __restrict__ coeffs,
                          const float* __restrict__ sigma,
                          float* __restrict__ out)
{
    __shared__ float4 s_basis[MAXROWS][2];

    const int tid  = threadIdx.x;
    const int lane = tid & 31;
    const int warp = tid >> 5;

    const int start = (blockIdx.x * BATCH) / GRID;
    const int len   = ((blockIdx.x + 1) * BATCH) / GRID - start;  // 6 or 7

    const float s     = fminf(fmaxf(sigma[0], 0.1f), 5.0f);
    const float inv_s = 1.0f / s;
    const float kexp  = -1.4426950408889634f * inv_s * inv_s;

    // ---- Phase 1: warps 0..len-1 each own one full row ----
    if (warp < len) {
        const int row = start + warp;
        const float4* xr =
            reinterpret_cast<const float4*>(x + (size_t)row * FEAT);

        float a[WIDTH];
        if (s == 1.0f) eval_row<true >(xr, lane, inv_s, kexp, a);
        else           eval_row<false>(xr, lane, inv_s, kexp, a);

        // warp-local reduction -> FINAL basis at lane 0
#pragma unroll
        for (int w = 0; w < WIDTH; ++w) {
#pragma unroll
            for (int off = 16; off > 0; off >>= 1)
                a[w] += __shfl_xor_sync(0xffffffffu, a[w], off);
        }
        if (lane == 0) {
            s_basis[warp][0] = make_float4(a[0], a[1], a[2], a[3]);
            s_basis[warp][1] = make_float4(a[4], a[5], a[6], 0.0f);
        }
    }

    // ---- coeff loads + one-time packing into column pairs ----
    // thread owns cols [4t, 4t+3]; cp01[w] = (c[col0][w], c[col1][w]),
    // cp23[w] = (c[col2][w], c[col3][w]). Packed ONCE, reused for all rows.
    u64 cp01[WIDTH], cp23[WIDTH];
    {
        float4 c[7];
        const float4* c4 = reinterpret_cast<const float4*>(
            coeffs + (size_t)(tid * 4) * WIDTH);
#pragma unroll
        for (int i = 0; i < 7; ++i) c[i] = c4[i];
        const float* cf = reinterpret_cast<const float*>(c);
#pragma unroll
        for (int w = 0; w < WIDTH; ++w) {
            cp01[w] = pack2(cf[w],          cf[WIDTH + w]);
            cp23[w] = pack2(cf[2*WIDTH + w], cf[3*WIDTH + w]);
        }
    }

    __syncthreads();   // the ONLY barrier

    // ---- Phase 2: len rows x 4 output columns, packed f32x2 ----
    float* outb = out + (size_t)start * OUTF;
#pragma unroll
    for (int r = 0; r < MAXROWS; ++r) {
        if (r < len) {
            const float4 b0 = s_basis[r][0];         // LDS.128 broadcast
            const float4 b1 = s_basis[r][1];
            const float bs[WIDTH] =
                { b0.x, b0.y, b0.z, b0.w, b1.x, b1.y, b1.z };

            u64 o01 = 0ull, o23 = 0ull;              // (+0,+0) packed accs
#pragma unroll
            for (int w = 0; w < WIDTH; ++w) {
                const u64 bw = pack2(bs[w], bs[w]);  // splat (alu pipe)
                o01 = fma2(bw, cp01[w], o01);        // 2 cols per issue
                o23 = fma2(bw, cp23[w], o23);
            }
            uf2 t0; t0.u = o01;
            uf2 t1; t1.u = o23;
            const float4 o = make_float4(t0.f.x, t0.f.y, t1.f.x, t1.f.y);
            reinterpret_cast<float4*>(outb + (size_t)r * OUTF)[tid] = o;
        }
    }
}

extern "C" void kernel_launch(void* const* d_in, const int* in_sizes, int n_in,
                              void* d_out, int out_size)
{
    const float* x      = (const float*)d_in[0];   // (4096, 1024)
    const float* coeffs = (const float*)d_in[1];   // (1024, 7)
    const float* sigma  = (const float*)d_in[2];   // (1,)
    float* out          = (float*)d_out;           // (4096, 1024)

    hermite_fused_kernel<<<GRID, THREADS>>>(x, coeffs, sigma, out);
}